// round 3
// baseline (speedup 1.0000x reference)
#include <cuda_runtime.h>
#include <math.h>

// ---------------- problem constants ----------------
#define NB   800          // 8*100 images
#define IMGD 128
#define H1   60           // conv1 out
#define P1   30           // pooled1
#define C1   4
#define H2   11           // conv2 out
#define P2   5
#define C2   8

// ---------------- device scratch (allowed: __device__ globals) ----------------
__device__ float  g_out1[NB*C1*H1*H1];     // 46 MB
__device__ float  g_pool1[NB*C1*P1*P1];    // 11.5 MB
__device__ float  g_out2[NB*C2*H2*H2];
__device__ float  g_pool2[NB*C2*P2*P2];
__device__ double g_stats1[8];             // sum[4], sumsq[4]
__device__ double g_stats2[16];            // sum[8], sumsq[8]
__device__ float  g_w2eff[4*81*8];         // [c][tap][oc]
__device__ float  g_b2eff[8];
__device__ float  g_fc1w[200*16];          // [k][j]
__device__ float  g_fc1b[16];
__device__ float  g_zR[NB*5];              // z0,z1,r00,r01,r11 per sample

// ---------------- K0: zero stat accumulators ----------------
__global__ void k_zero() {
    int t = threadIdx.x;
    if (t < 8)  g_stats1[t] = 0.0;
    if (t < 16) g_stats2[t] = 0.0;
}

// ---------------- K1: conv1 + bias + relu ----------------
// smem: [0..975] weights transposed [tap(243)][oc(4)], then input planar
// sin[c][y][ (col&1)*64 + col>>1 ], y in 0..126
#define SM1_W     976
#define SM1_IN    (3*127*128)
#define SM1_FLOATS (SM1_W + SM1_IN)
#define SM1_BYTES (SM1_FLOATS*4)

__global__ __launch_bounds__(256, 1)
void k_conv1(const float* __restrict__ x, const float* __restrict__ w1,
             const float* __restrict__ b1) {
    extern __shared__ float sm[];
    float* sw  = sm;            // 16B aligned at base
    float* sin = sm + SM1_W;
    const int n = blockIdx.x;
    const int tid = threadIdx.x;

    // weights transposed: sw[tap*4+oc] = w1[oc][c][ky][kx], tap = c*81 + ky*9+kx
    for (int i = tid; i < 972; i += 256) {
        int oc = i & 3, tap = i >> 2;
        int c = tap / 81, r = tap - c*81;
        sw[i] = w1[(oc*3 + c)*81 + r];
    }
    // input: rows/cols 0..126 used (load full 127x128x3 region linearly)
    const float* xb = x + (size_t)n * (IMGD*IMGD*3);
    for (int i = tid; i < SM1_IN; i += 256) {
        int y = i / 384; int rem = i - y*384;
        int col = rem / 3; int c = rem - col*3;
        sin[(c*127 + y)*128 + ((col & 1) << 6) + (col >> 1)] = xb[i];
    }
    __syncthreads();

    const int warp = tid >> 5, lane = tid & 31;
    const int seg = warp & 1, rg = warp >> 1;
    const int lx = (lane < 30) ? lane : 29;     // clamp idle lanes (safe addrs)
    const int ox = seg*30 + lx;
    const bool active = (lane < 30);
    const float bb0 = b1[0], bb1 = b1[1], bb2 = b1[2], bb3 = b1[3];

    for (int pass = 0; pass < 3; ++pass) {
        const int oy0 = (pass*4 + rg) * 5;      // 5 rows per warp-pass
        float acc[5][4];
        #pragma unroll
        for (int r = 0; r < 5; ++r) { acc[r][0]=acc[r][1]=acc[r][2]=acc[r][3]=0.f; }

        for (int c = 0; c < 3; ++c) {
            for (int ky = 0; ky < 9; ++ky) {
                const float* rowbase = &sin[(c*127 + 2*oy0 + ky)*128];
                const float4* wrow = (const float4*)&sw[(c*9 + ky)*36];
                #pragma unroll
                for (int kx = 0; kx < 9; ++kx) {
                    float4 w4 = wrow[kx];
                    int scol = ((kx & 1) << 6) + ox + (kx >> 1);
                    #pragma unroll
                    for (int r = 0; r < 5; ++r) {
                        float v = rowbase[r*256 + scol];   // row advances by 2
                        acc[r][0] = fmaf(v, w4.x, acc[r][0]);
                        acc[r][1] = fmaf(v, w4.y, acc[r][1]);
                        acc[r][2] = fmaf(v, w4.z, acc[r][2]);
                        acc[r][3] = fmaf(v, w4.w, acc[r][3]);
                    }
                }
            }
        }
        if (active) {
            #pragma unroll
            for (int r = 0; r < 5; ++r) {
                int oy = oy0 + r;
                size_t base = (((size_t)n*4)*60 + oy)*60 + ox;
                g_out1[base          ] = fmaxf(acc[r][0] + bb0, 0.f);
                g_out1[base + 3600ull] = fmaxf(acc[r][1] + bb1, 0.f);
                g_out1[base + 7200ull] = fmaxf(acc[r][2] + bb2, 0.f);
                g_out1[base + 10800ull]= fmaxf(acc[r][3] + bb3, 0.f);
            }
        }
    }
}

// ---------------- K2: maxpool1 + bn1 stats ----------------
__global__ __launch_bounds__(256)
void k_pool1() {
    const int n = blockIdx.x, tid = threadIdx.x;
    const int c = tid >> 6, sub = tid & 63;          // 64 threads per channel
    const float* src = g_out1  + ((size_t)n*4 + c)*3600;
    float*       dst = g_pool1 + ((size_t)n*4 + c)*900;
    float s1 = 0.f, s2 = 0.f;
    for (int i = sub; i < 900; i += 64) {
        int py = i / 30, px = i - py*30;
        const float* r0 = src + (2*py)*60 + 2*px;
        float2 a = *(const float2*)r0;
        float2 b = *(const float2*)(r0 + 60);
        float m = fmaxf(fmaxf(a.x, a.y), fmaxf(b.x, b.y));
        dst[i] = m; s1 += m; s2 += m*m;
    }
    #pragma unroll
    for (int off = 16; off; off >>= 1) {
        s1 += __shfl_down_sync(0xffffffffu, s1, off);
        s2 += __shfl_down_sync(0xffffffffu, s2, off);
    }
    if ((tid & 31) == 0) {
        atomicAdd(&g_stats1[c],     (double)s1);
        atomicAdd(&g_stats1[4 + c], (double)s2);
    }
}

// ---------------- K3: finalize bn1, fold into conv2 weights ----------------
__global__ void k_fold1(const float* __restrict__ w2, const float* __restrict__ b2,
                        const float* __restrict__ g, const float* __restrict__ bt) {
    __shared__ float a1[4], sh1[4];
    const int tid = threadIdx.x;
    if (tid < 4) {
        double invn = 1.0 / (800.0 * 900.0);
        float mean = (float)(g_stats1[tid] * invn);
        float var  = (float)(g_stats1[4+tid] * invn) - mean*mean;
        float a = g[tid] * rsqrtf(var + 1e-5f);
        a1[tid] = a; sh1[tid] = bt[tid] - mean * a;
    }
    __syncthreads();
    for (int i = tid; i < 2592; i += blockDim.x) {
        int o = i & 7, rest = i >> 3;          // rest = c*81 + tap
        int c = rest / 81, tap = rest - c*81;
        g_w2eff[i] = w2[(o*4 + c)*81 + tap] * a1[c];
    }
    if (tid < 8) {
        float s = b2[tid];
        for (int c = 0; c < 4; ++c) {
            float acc = 0.f;
            for (int t = 0; t < 81; ++t) acc += w2[(tid*4 + c)*81 + t];
            s += acc * sh1[c];
        }
        g_b2eff[tid] = s;
    }
}

// ---------------- K4: conv2 (bn1 folded) + bias + relu ----------------
__global__ __launch_bounds__(128)
void k_conv2() {
    __shared__ float sp[4*30*33];                 // padded rows, even/odd cols
    __shared__ __align__(16) float sw[2592];
    __shared__ float sb[8];
    const int n = blockIdx.x, tid = threadIdx.x;
    const float* src = g_pool1 + (size_t)n*3600;
    for (int i = tid; i < 3600; i += 128) {
        int c = i / 900; int rem = i - c*900;
        int y = rem / 30; int col = rem - y*30;
        sp[(c*30 + y)*33 + ((col & 1) << 4) + (col >> 1)] = src[i];
    }
    for (int i = tid; i < 2592; i += 128) sw[i] = g_w2eff[i];
    if (tid < 8) sb[tid] = g_b2eff[tid];
    __syncthreads();
    if (tid < 121) {
        const int oy = tid / 11, ox = tid - oy*11;
        float acc[8];
        #pragma unroll
        for (int o = 0; o < 8; ++o) acc[o] = 0.f;
        for (int c = 0; c < 4; ++c) {
            for (int ky = 0; ky < 9; ++ky) {
                const float* rb = &sp[(c*30 + 2*oy + ky)*33];
                const float4* wr = (const float4*)&sw[(c*81 + ky*9)*8];
                #pragma unroll
                for (int kx = 0; kx < 9; ++kx) {
                    float v = rb[((kx & 1) << 4) + ox + (kx >> 1)];
                    float4 w0 = wr[kx*2], w1 = wr[kx*2 + 1];
                    acc[0] = fmaf(v, w0.x, acc[0]); acc[1] = fmaf(v, w0.y, acc[1]);
                    acc[2] = fmaf(v, w0.z, acc[2]); acc[3] = fmaf(v, w0.w, acc[3]);
                    acc[4] = fmaf(v, w1.x, acc[4]); acc[5] = fmaf(v, w1.y, acc[5]);
                    acc[6] = fmaf(v, w1.z, acc[6]); acc[7] = fmaf(v, w1.w, acc[7]);
                }
            }
        }
        float* dst = g_out2 + (size_t)n*8*121;
        #pragma unroll
        for (int o = 0; o < 8; ++o)
            dst[o*121 + tid] = fmaxf(acc[o] + sb[o], 0.f);
    }
}

// ---------------- K5: maxpool2 + bn2 stats ----------------
__global__ __launch_bounds__(64)
void k_pool2() {
    const int n = blockIdx.x, tid = threadIdx.x;
    const int c = tid >> 3, sub = tid & 7;
    const float* src = g_out2  + ((size_t)n*8 + c)*121;
    float*       dst = g_pool2 + ((size_t)n*8 + c)*25;
    float s1 = 0.f, s2 = 0.f;
    for (int i = sub; i < 25; i += 8) {
        int py = i / 5, px = i - py*5;
        const float* r0 = src + 2*py*11 + 2*px;
        float m = fmaxf(fmaxf(r0[0], r0[1]), fmaxf(r0[11], r0[12]));
        dst[i] = m; s1 += m; s2 += m*m;
    }
    #pragma unroll
    for (int off = 4; off; off >>= 1) {
        s1 += __shfl_down_sync(0xffffffffu, s1, off, 8);
        s2 += __shfl_down_sync(0xffffffffu, s2, off, 8);
    }
    if (sub == 0) {
        atomicAdd(&g_stats2[c],     (double)s1);
        atomicAdd(&g_stats2[8 + c], (double)s2);
    }
}

// ---------------- K6: finalize bn2, fold into fc1 ----------------
__global__ void k_fold2(const float* __restrict__ fc1w, const float* __restrict__ fc1b,
                        const float* __restrict__ g, const float* __restrict__ bt) {
    __shared__ float a2[8], sh2[8];
    const int tid = threadIdx.x;
    if (tid < 8) {
        double invn = 1.0 / 20000.0;
        float mean = (float)(g_stats2[tid] * invn);
        float var  = (float)(g_stats2[8+tid] * invn) - mean*mean;
        float a = g[tid] * rsqrtf(var + 1e-5f);
        a2[tid] = a; sh2[tid] = bt[tid] - mean * a;
    }
    __syncthreads();
    for (int i = tid; i < 3200; i += blockDim.x) {
        int j = i & 15, k = i >> 4;
        g_fc1w[i] = fc1w[j*200 + k] * a2[k / 25];
    }
    if (tid < 16) {
        float s = fc1b[tid];
        for (int k = 0; k < 200; ++k) s += fc1w[tid*200 + k] * sh2[k / 25];
        g_fc1b[tid] = s;
    }
}

// ---------------- K7: FC chain -> z, R ----------------
__global__ __launch_bounds__(64)
void k_fc(const float* __restrict__ fc2w, const float* __restrict__ fc2b,
          const float* __restrict__ zw, const float* __restrict__ zb,
          const float* __restrict__ Lw, const float* __restrict__ Lb) {
    __shared__ __align__(16) float s_w1[3200];
    __shared__ float s_b1[16], s_w2[512], s_b2[32], s_zw[64], s_zb[2], s_Lw[96], s_Lb[3];
    const int tid = threadIdx.x;
    for (int i = tid; i < 3200; i += 64) s_w1[i] = g_fc1w[i];
    if (tid < 16) s_b1[tid] = g_fc1b[tid];
    for (int i = tid; i < 512; i += 64) s_w2[i] = fc2w[i];
    if (tid < 32) s_b2[tid] = fc2b[tid];
    s_zw[tid] = zw[tid];
    if (tid < 2) s_zb[tid] = zb[tid];
    for (int i = tid; i < 96; i += 64) s_Lw[i] = Lw[i];
    if (tid < 3) s_Lb[tid] = Lb[tid];
    __syncthreads();
    const int s = blockIdx.x*64 + tid;
    if (s >= NB) return;
    const float* f = g_pool2 + (size_t)s*200;
    float h1[16];
    #pragma unroll
    for (int j = 0; j < 16; ++j) h1[j] = s_b1[j];
    for (int k = 0; k < 200; ++k) {
        float v = f[k];
        const float4* wr = (const float4*)&s_w1[k*16];
        float4 w0 = wr[0], w1 = wr[1], w2 = wr[2], w3 = wr[3];
        h1[0] = fmaf(v, w0.x, h1[0]);  h1[1] = fmaf(v, w0.y, h1[1]);
        h1[2] = fmaf(v, w0.z, h1[2]);  h1[3] = fmaf(v, w0.w, h1[3]);
        h1[4] = fmaf(v, w1.x, h1[4]);  h1[5] = fmaf(v, w1.y, h1[5]);
        h1[6] = fmaf(v, w1.z, h1[6]);  h1[7] = fmaf(v, w1.w, h1[7]);
        h1[8] = fmaf(v, w2.x, h1[8]);  h1[9] = fmaf(v, w2.y, h1[9]);
        h1[10]= fmaf(v, w2.z, h1[10]); h1[11]= fmaf(v, w2.w, h1[11]);
        h1[12]= fmaf(v, w3.x, h1[12]); h1[13]= fmaf(v, w3.y, h1[13]);
        h1[14]= fmaf(v, w3.z, h1[14]); h1[15]= fmaf(v, w3.w, h1[15]);
    }
    #pragma unroll
    for (int j = 0; j < 16; ++j) h1[j] = fmaxf(h1[j], 0.f);
    float h2[32];
    #pragma unroll
    for (int j = 0; j < 32; ++j) {
        float a = s_b2[j];
        #pragma unroll
        for (int k = 0; k < 16; ++k) a = fmaf(s_w2[j*16 + k], h1[k], a);
        h2[j] = fmaxf(a, 0.f);
    }
    float z0 = s_zb[0], z1 = s_zb[1], L0 = s_Lb[0], L1 = s_Lb[1], L2 = s_Lb[2];
    #pragma unroll
    for (int k = 0; k < 32; ++k) {
        z0 = fmaf(s_zw[k],      h2[k], z0);
        z1 = fmaf(s_zw[32 + k], h2[k], z1);
        L0 = fmaf(s_Lw[k],      h2[k], L0);
        L1 = fmaf(s_Lw[32 + k], h2[k], L1);
        L2 = fmaf(s_Lw[64 + k], h2[k], L2);
    }
    float* o = g_zR + (size_t)s*5;
    o[0] = z0; o[1] = z1;
    o[2] = L0*L0; o[3] = L0*L1; o[4] = L1*L1 + L2*L2;
}

// ---------------- K8: Kalman filter (1 warp, 1 thread/sequence) ----------------
__device__ __forceinline__ constexpr int SIDX(int i, int j) {
    return (i <= j) ? (i*(7 - i))/2 + j : (j*(7 - j))/2 + i;
}
#define S_(i,j)  sarr[SIDX(i,j)]
#define SP_(i,j) sp[SIDX(i,j)]

__global__ __launch_bounds__(32)
void k_kf(const float* __restrict__ A_, const float* __restrict__ B_,
          const float* __restrict__ C_, const float* __restrict__ Q_,
          float* __restrict__ out) {
    __shared__ float sz[NB*5];
    __shared__ float sA[16], sC[8], sBQ[16];
    const int tid = threadIdx.x;
    for (int i = tid; i < NB*5; i += 32) sz[i] = g_zR[i];
    if (tid < 16) sA[tid] = A_[tid];
    if (tid < 8)  sC[tid] = C_[tid];
    if (tid == 0) {
        float BQ[8];
        for (int i = 0; i < 4; ++i)
            for (int a = 0; a < 2; ++a)
                BQ[i*2+a] = B_[i*2]*Q_[a] + B_[i*2+1]*Q_[2+a];
        for (int i = 0; i < 4; ++i)
            for (int j = 0; j < 4; ++j)
                sBQ[i*4+j] = BQ[i*2]*B_[j*2] + BQ[i*2+1]*B_[j*2+1];
    }
    __syncthreads();
    if (tid >= 8) return;
    const int b = tid;
    float A[16], C[8], BQ[16];
    #pragma unroll
    for (int i = 0; i < 16; ++i) A[i] = sA[i];
    #pragma unroll
    for (int i = 0; i < 8;  ++i) C[i] = sC[i];
    #pragma unroll
    for (int i = 0; i < 16; ++i) BQ[i] = sBQ[i];

    const float* zr = sz + b*500;
    float h[4], sarr[10];
    h[0] = zr[0]; h[1] = zr[1]; h[2] = 0.f; h[3] = 0.f;
    sarr[0] = zr[2]; sarr[1] = zr[3]; sarr[2] = 0.f; sarr[3] = 0.f;
    sarr[4] = zr[4]; sarr[5] = 0.f;  sarr[6] = 0.f;
    sarr[7] = 1.f;   sarr[8] = 0.f;  sarr[9] = 1.f;

    float* ob = out + b*400;
    ob[0]=h[0]; ob[1]=h[1]; ob[2]=h[2]; ob[3]=h[3];

    for (int t = 1; t < 100; ++t) {
        const float* p = zr + t*5;
        float zt0 = p[0], zt1 = p[1], r00 = p[2], r01 = p[3], r11 = p[4];
        float hp[4];
        #pragma unroll
        for (int i = 0; i < 4; ++i)
            hp[i] = A[i*4]*h[0] + A[i*4+1]*h[1] + A[i*4+2]*h[2] + A[i*4+3]*h[3];
        float M[16];
        #pragma unroll
        for (int i = 0; i < 4; ++i)
            #pragma unroll
            for (int j = 0; j < 4; ++j)
                M[i*4+j] = A[i*4]*S_(0,j) + A[i*4+1]*S_(1,j)
                         + A[i*4+2]*S_(2,j) + A[i*4+3]*S_(3,j);
        float sp[10];
        #pragma unroll
        for (int i = 0; i < 4; ++i)
            #pragma unroll
            for (int j = 0; j < 4; ++j)
                if (j >= i)
                    sp[SIDX(i,j)] = M[i*4]*A[j*4] + M[i*4+1]*A[j*4+1]
                                  + M[i*4+2]*A[j*4+2] + M[i*4+3]*A[j*4+3] + BQ[i*4+j];
        float PT[8];   // sp @ C^T : [i][a]
        #pragma unroll
        for (int i = 0; i < 4; ++i)
            #pragma unroll
            for (int a = 0; a < 2; ++a)
                PT[i*2+a] = SP_(i,0)*C[a*4] + SP_(i,1)*C[a*4+1]
                          + SP_(i,2)*C[a*4+2] + SP_(i,3)*C[a*4+3];
        float S00 = C[0]*PT[0]+C[1]*PT[2]+C[2]*PT[4]+C[3]*PT[6] + r00;
        float S01 = C[0]*PT[1]+C[1]*PT[3]+C[2]*PT[5]+C[3]*PT[7] + r01;
        float S10 = C[4]*PT[0]+C[5]*PT[2]+C[6]*PT[4]+C[7]*PT[6] + r01;
        float S11 = C[4]*PT[1]+C[5]*PT[3]+C[6]*PT[5]+C[7]*PT[7] + r11;
        float inv = 1.0f / (S00*S11 - S01*S10);
        float i00 =  S11*inv, i01 = -S01*inv, i10 = -S10*inv, i11 = S00*inv;
        float K[8];
        #pragma unroll
        for (int i = 0; i < 4; ++i) {
            K[i*2]   = PT[i*2]*i00 + PT[i*2+1]*i10;
            K[i*2+1] = PT[i*2]*i01 + PT[i*2+1]*i11;
        }
        float al0 = zt0 - (C[0]*hp[0]+C[1]*hp[1]+C[2]*hp[2]+C[3]*hp[3]);
        float al1 = zt1 - (C[4]*hp[0]+C[5]*hp[1]+C[6]*hp[2]+C[7]*hp[3]);
        #pragma unroll
        for (int i = 0; i < 4; ++i) h[i] = hp[i] + K[i*2]*al0 + K[i*2+1]*al1;
        float sn[10];
        #pragma unroll
        for (int i = 0; i < 4; ++i)
            #pragma unroll
            for (int j = 0; j < 4; ++j)
                if (j >= i)
                    sn[SIDX(i,j)] = SP_(i,j) - K[i*2]*PT[j*2] - K[i*2+1]*PT[j*2+1];
        #pragma unroll
        for (int i = 0; i < 10; ++i) sarr[i] = sn[i];
        float* op = ob + t*4;
        op[0]=h[0]; op[1]=h[1]; op[2]=h[2]; op[3]=h[3];
    }
}

// ---------------- launch ----------------
extern "C" void kernel_launch(void* const* d_in, const int* in_sizes, int n_in,
                              void* d_out, int out_size) {
    (void)in_sizes; (void)n_in; (void)out_size;
    const float* x    = (const float*)d_in[0];
    const float* w1   = (const float*)d_in[1];
    const float* b1   = (const float*)d_in[2];
    const float* bn1g = (const float*)d_in[3];
    const float* bn1b = (const float*)d_in[4];
    const float* w2   = (const float*)d_in[5];
    const float* b2   = (const float*)d_in[6];
    const float* bn2g = (const float*)d_in[7];
    const float* bn2b = (const float*)d_in[8];
    const float* fc1w = (const float*)d_in[9];
    const float* fc1b = (const float*)d_in[10];
    const float* fc2w = (const float*)d_in[11];
    const float* fc2b = (const float*)d_in[12];
    const float* f3zw = (const float*)d_in[13];
    const float* f3zb = (const float*)d_in[14];
    const float* f3Lw = (const float*)d_in[15];
    const float* f3Lb = (const float*)d_in[16];
    const float* Am   = (const float*)d_in[17];
    const float* Bm   = (const float*)d_in[18];
    const float* Cm   = (const float*)d_in[19];
    const float* Qm   = (const float*)d_in[20];

    (void)cudaFuncSetAttribute(k_conv1, cudaFuncAttributeMaxDynamicSharedMemorySize, SM1_BYTES);

    k_zero <<<1, 32>>>();
    k_conv1<<<NB, 256, SM1_BYTES>>>(x, w1, b1);
    k_pool1<<<NB, 256>>>();
    k_fold1<<<1, 256>>>(w2, b2, bn1g, bn1b);
    k_conv2<<<NB, 128>>>();
    k_pool2<<<NB, 64>>>();
    k_fold2<<<1, 256>>>(fc1w, fc1b, bn2g, bn2b);
    k_fc   <<<13, 64>>>(fc2w, fc2b, f3zw, f3zb, f3Lw, f3Lb);
    k_kf   <<<1, 32>>>(Am, Bm, Cm, Qm, (float*)d_out);
}

// round 5
// speedup vs baseline: 1.5822x; 1.5822x over previous
#include <cuda_runtime.h>
#include <math.h>

// ---------------- problem constants ----------------
#define NB   800          // 8*100 images
#define IMGD 128

// ---------------- device scratch ----------------
__device__ float  g_pool1[NB*4*30*30];     // 11.5 MB
__device__ float  g_pool2[NB*8*5*5];
__device__ double g_stats1[8];             // sum[4], sumsq[4]
__device__ double g_stats2[16];            // sum[8], sumsq[8]
__device__ float  g_zR[NB*5];              // z0,z1,r00,r01,r11 per sample

// ---------------- f32x2 helpers ----------------
typedef unsigned long long ull;
__device__ __forceinline__ ull pack2(float a, float b) {
    ull r; asm("mov.b64 %0, {%1,%2};" : "=l"(r) : "f"(a), "f"(b)); return r;
}
__device__ __forceinline__ void unpack2(ull v, float& a, float& b) {
    asm("mov.b64 {%0,%1}, %2;" : "=f"(a), "=f"(b) : "l"(v));
}
__device__ __forceinline__ ull ffma2(ull a, ull b, ull c) {
    ull d; asm("fma.rn.f32x2 %0, %1, %2, %3;" : "=l"(d) : "l"(a), "l"(b), "l"(c));
    return d;
}

// ---------------- K0: zero stat accumulators ----------------
__global__ void k_zero() {
    int t = threadIdx.x;
    if (t < 8)  g_stats1[t] = 0.0;
    if (t < 16) g_stats2[t] = 0.0;
}

// ---------------- K1: conv1 + bias + relu + maxpool + bn1 stats ----------------
// 5 bands per image, 12 output rows per band. Input: 31 rows x 128 cols x 3 ch.
// smem layout (floats): [0,976) weights [tap(243)][oc(4)]; [976, 976+11904) input
// planar si[c][y][(col&1)*64 + (col>>1)] (c-plane 31*128); reused as out tile
// sout[oc][12][60] after compute; [12880,12896) stat partials.
#define SM1_W      976
#define SM1_IN     (3*31*128)
#define SM1_FLOATS (SM1_W + SM1_IN + 16)
#define SM1_BYTES  (SM1_FLOATS*4)

__global__ __launch_bounds__(256, 1)
void k_conv1(const float* __restrict__ x, const float* __restrict__ w1,
             const float* __restrict__ b1) {
    extern __shared__ float sm[];
    float* sw = sm;
    float* si = sm + SM1_W;
    float* ps = sm + SM1_W + SM1_IN;   // 16 partials: s1[8 warps], s2[8 warps]
    const int bx = blockIdx.x;
    const int n = bx / 5, band = bx - n*5;
    const int tid = threadIdx.x;

    // weights transposed: sw[tap*4+oc]
    for (int i = tid; i < 972; i += 256) {
        int oc = i & 3, tap = i >> 2;
        int c = tap / 81, r = tap - c*81;
        sw[i] = w1[(oc*3 + c)*81 + r];
    }
    // input rows [24*band, 24*band+31), contiguous 11904 floats from x
    const float4* xb4 = (const float4*)(x + (size_t)n*(IMGD*IMGD*3) + (size_t)(24*band)*384);
    for (int i = tid; i < SM1_IN/4; i += 256) {
        float4 v = xb4[i];
        int j = i*4;
        #pragma unroll
        for (int e = 0; e < 4; ++e) {
            int jj = j + e;
            int y = jj / 384; int rem = jj - y*384;
            int col = rem / 3; int c = rem - col*3;
            float val = (e==0) ? v.x : (e==1) ? v.y : (e==2) ? v.z : v.w;
            si[(c*31 + y)*128 + ((col & 1) << 6) + (col >> 1)] = val;
        }
    }
    __syncthreads();

    const int warp = tid >> 5, lane = tid & 31;
    const int seg = warp & 1, rg = warp >> 1;        // rg in 0..3, 3 rows each
    const int lx = (lane < 30) ? lane : 29;
    const int ox = seg*30 + lx;
    const bool active = (lane < 30);

    ull acc01[3] = {0ull, 0ull, 0ull};
    ull acc23[3] = {0ull, 0ull, 0ull};

    for (int c = 0; c < 3; ++c) {
        for (int ky = 0; ky < 9; ++ky) {
            const float* rowbase = &si[(c*31 + 6*rg + ky)*128];
            const ull* wrow = (const ull*)&sw[(c*9 + ky)*36];
            #pragma unroll
            for (int kx = 0; kx < 9; ++kx) {
                ull w01 = wrow[kx*2], w23 = wrow[kx*2 + 1];
                int scol = ((kx & 1) << 6) + ox + (kx >> 1);
                #pragma unroll
                for (int r = 0; r < 3; ++r) {
                    float v = rowbase[r*256 + scol];
                    ull vv = pack2(v, v);
                    acc01[r] = ffma2(vv, w01, acc01[r]);
                    acc23[r] = ffma2(vv, w23, acc23[r]);
                }
            }
        }
    }
    const float bb0 = b1[0], bb1 = b1[1], bb2 = b1[2], bb3 = b1[3];
    __syncthreads();                     // all reads of si done
    float* sout = si;                    // alias: sout[oc*720 + row*60 + col]
    if (active) {
        #pragma unroll
        for (int r = 0; r < 3; ++r) {
            float a0, a1v, a2, a3;
            unpack2(acc01[r], a0, a1v);
            unpack2(acc23[r], a2, a3);
            int row = 3*rg + r;
            sout[       row*60 + ox] = fmaxf(a0 + bb0, 0.f);
            sout[ 720 + row*60 + ox] = fmaxf(a1v + bb1, 0.f);
            sout[1440 + row*60 + ox] = fmaxf(a2 + bb2, 0.f);
            sout[2160 + row*60 + ox] = fmaxf(a3 + bb3, 0.f);
        }
    }
    __syncthreads();

    // pool 2x2: warp w handles channel oc=w>>1, half=w&1 -> 90 of 180 items
    {
        const int oc = warp >> 1, half = warp & 1;
        float s1 = 0.f, s2 = 0.f;
        for (int i = half*90 + lane; i < half*90 + 90; i += 32) {
            int pr = i / 30, pc = i - pr*30;
            const float* b0 = &sout[oc*720 + (2*pr)*60 + 2*pc];
            float2 t0 = *(const float2*)b0;
            float2 t1 = *(const float2*)(b0 + 60);
            float m = fmaxf(fmaxf(t0.x, t0.y), fmaxf(t1.x, t1.y));
            g_pool1[((size_t)n*4 + oc)*900 + (6*band + pr)*30 + pc] = m;
            s1 += m; s2 += m*m;
        }
        #pragma unroll
        for (int off = 16; off; off >>= 1) {
            s1 += __shfl_down_sync(0xffffffffu, s1, off);
            s2 += __shfl_down_sync(0xffffffffu, s2, off);
        }
        if (lane == 0) { ps[warp] = s1; ps[8 + warp] = s2; }
    }
    __syncthreads();
    if (tid < 4) {
        atomicAdd(&g_stats1[tid],     (double)(ps[2*tid] + ps[2*tid+1]));
        atomicAdd(&g_stats1[4 + tid], (double)(ps[8 + 2*tid] + ps[8 + 2*tid+1]));
    }
}

// ---------------- K2: fold bn1 + conv2 + relu + maxpool + bn2 stats ----------------
__global__ __launch_bounds__(128)
void k_conv2(const float* __restrict__ w2, const float* __restrict__ b2,
             const float* __restrict__ g1, const float* __restrict__ bt1) {
    __shared__ float sp[4*30*33];
    __shared__ __align__(16) float sw[2592];
    __shared__ float sout[8*121];
    __shared__ float a1[4], sh1[4], b2e[8], sstat[16];
    const int n = blockIdx.x, tid = threadIdx.x;

    if (tid < 4) {
        double invn = 1.0 / (800.0 * 900.0);
        float mean = (float)(g_stats1[tid] * invn);
        float var  = (float)(g_stats1[4+tid] * invn) - mean*mean;
        float a = g1[tid] * rsqrtf(var + 1e-5f);
        a1[tid] = a; sh1[tid] = bt1[tid] - mean * a;
    }
    if (tid < 16) sstat[tid] = 0.f;
    __syncthreads();

    const float* src = g_pool1 + (size_t)n*3600;
    for (int i = tid; i < 3600; i += 128) {
        int c = i / 900; int rem = i - c*900;
        int y = rem / 30; int col = rem - y*30;
        sp[(c*30 + y)*33 + ((col & 1) << 4) + (col >> 1)] = src[i];
    }
    for (int i = tid; i < 2592; i += 128) {
        int o = i & 7, rest = i >> 3;
        int c = rest / 81, tap = rest - c*81;
        sw[i] = w2[(o*4 + c)*81 + tap] * a1[c];
    }
    if (tid < 8) {
        float s = b2[tid];
        for (int c = 0; c < 4; ++c) {
            float acc = 0.f;
            for (int t = 0; t < 81; ++t) acc += w2[(tid*4 + c)*81 + t];
            s += acc * sh1[c];
        }
        b2e[tid] = s;
    }
    __syncthreads();

    if (tid < 121) {
        const int oy = tid / 11, ox = tid - oy*11;
        ull acc[4] = {0ull, 0ull, 0ull, 0ull};
        for (int c = 0; c < 4; ++c) {
            for (int ky = 0; ky < 9; ++ky) {
                const float* rb = &sp[(c*30 + 2*oy + ky)*33];
                const ull* wr = (const ull*)&sw[(c*81 + ky*9)*8];
                #pragma unroll
                for (int kx = 0; kx < 9; ++kx) {
                    float v = rb[((kx & 1) << 4) + ox + (kx >> 1)];
                    ull vv = pack2(v, v);
                    acc[0] = ffma2(vv, wr[kx*4    ], acc[0]);
                    acc[1] = ffma2(vv, wr[kx*4 + 1], acc[1]);
                    acc[2] = ffma2(vv, wr[kx*4 + 2], acc[2]);
                    acc[3] = ffma2(vv, wr[kx*4 + 3], acc[3]);
                }
            }
        }
        #pragma unroll
        for (int p = 0; p < 4; ++p) {
            float lo, hi; unpack2(acc[p], lo, hi);
            sout[(2*p  )*121 + tid] = fmaxf(lo + b2e[2*p  ], 0.f);
            sout[(2*p+1)*121 + tid] = fmaxf(hi + b2e[2*p+1], 0.f);
        }
    }
    __syncthreads();

    for (int i = tid; i < 200; i += 128) {
        int oc = i / 25, j = i - oc*25;
        int py = j / 5, px = j - py*5;
        const float* r0 = &sout[oc*121 + 2*py*11 + 2*px];
        float m = fmaxf(fmaxf(r0[0], r0[1]), fmaxf(r0[11], r0[12]));
        g_pool2[((size_t)n*8 + oc)*25 + j] = m;
        atomicAdd(&sstat[oc], m);
        atomicAdd(&sstat[8 + oc], m*m);
    }
    __syncthreads();
    if (tid < 16) atomicAdd(&g_stats2[tid], (double)sstat[tid]);
}

// ---------------- K3: fold bn2 + FC chain -> z, R ----------------
__global__ __launch_bounds__(64)
void k_fc(const float* __restrict__ fc1w, const float* __restrict__ fc1b,
          const float* __restrict__ fc2w, const float* __restrict__ fc2b,
          const float* __restrict__ zw, const float* __restrict__ zb,
          const float* __restrict__ Lw, const float* __restrict__ Lb,
          const float* __restrict__ g2, const float* __restrict__ bt2) {
    __shared__ __align__(16) float s_w1[3200];
    __shared__ float s_b1[16], s_w2[512], s_b2[32], s_zw[64], s_zb[2], s_Lw[96], s_Lb[3];
    __shared__ float a2[8], sh2[8];
    const int tid = threadIdx.x;
    if (tid < 8) {
        double invn = 1.0 / 20000.0;
        float mean = (float)(g_stats2[tid] * invn);
        float var  = (float)(g_stats2[8+tid] * invn) - mean*mean;
        float a = g2[tid] * rsqrtf(var + 1e-5f);
        a2[tid] = a; sh2[tid] = bt2[tid] - mean * a;
    }
    __syncthreads();
    for (int i = tid; i < 3200; i += 64) {
        int j = i & 15, k = i >> 4;
        s_w1[i] = fc1w[j*200 + k] * a2[k / 25];
    }
    if (tid < 16) {
        float s = fc1b[tid];
        for (int k = 0; k < 200; ++k) s += fc1w[tid*200 + k] * sh2[k / 25];
        s_b1[tid] = s;
    }
    for (int i = tid; i < 512; i += 64) s_w2[i] = fc2w[i];
    if (tid < 32) s_b2[tid] = fc2b[tid];
    s_zw[tid] = zw[tid];
    if (tid < 2) s_zb[tid] = zb[tid];
    for (int i = tid; i < 96; i += 64) s_Lw[i] = Lw[i];
    if (tid < 3) s_Lb[tid] = Lb[tid];
    __syncthreads();

    const int s = blockIdx.x*64 + tid;
    if (s >= NB) return;
    const float* f = g_pool2 + (size_t)s*200;
    ull hacc[8];
    #pragma unroll
    for (int j = 0; j < 8; ++j) hacc[j] = pack2(s_b1[2*j], s_b1[2*j+1]);
    for (int k = 0; k < 200; ++k) {
        float v = f[k];
        ull vv = pack2(v, v);
        const ull* wr = (const ull*)&s_w1[k*16];
        #pragma unroll
        for (int j = 0; j < 8; ++j) hacc[j] = ffma2(vv, wr[j], hacc[j]);
    }
    float h1[16];
    #pragma unroll
    for (int j = 0; j < 8; ++j) {
        float lo, hi; unpack2(hacc[j], lo, hi);
        h1[2*j] = fmaxf(lo, 0.f); h1[2*j+1] = fmaxf(hi, 0.f);
    }
    float h2[32];
    #pragma unroll
    for (int j = 0; j < 32; ++j) {
        float a = s_b2[j];
        #pragma unroll
        for (int k = 0; k < 16; ++k) a = fmaf(s_w2[j*16 + k], h1[k], a);
        h2[j] = fmaxf(a, 0.f);
    }
    float z0 = s_zb[0], z1 = s_zb[1], L0 = s_Lb[0], L1 = s_Lb[1], L2 = s_Lb[2];
    #pragma unroll
    for (int k = 0; k < 32; ++k) {
        z0 = fmaf(s_zw[k],      h2[k], z0);
        z1 = fmaf(s_zw[32 + k], h2[k], z1);
        L0 = fmaf(s_Lw[k],      h2[k], L0);
        L1 = fmaf(s_Lw[32 + k], h2[k], L1);
        L2 = fmaf(s_Lw[64 + k], h2[k], L2);
    }
    float* o = g_zR + (size_t)s*5;
    o[0] = z0; o[1] = z1;
    o[2] = L0*L0; o[3] = L0*L1; o[4] = L1*L1 + L2*L2;
}

// ---------------- K4: Kalman filter (1 warp, 1 thread/sequence) ----------------
__device__ __forceinline__ constexpr int SIDX(int i, int j) {
    return (i <= j) ? (i*(7 - i))/2 + j : (j*(7 - j))/2 + i;
}
#define S_(i,j)  sarr[SIDX(i,j)]
#define SP_(i,j) sp[SIDX(i,j)]

__global__ __launch_bounds__(32)
void k_kf(const float* __restrict__ A_, const float* __restrict__ B_,
          const float* __restrict__ C_, const float* __restrict__ Q_,
          float* __restrict__ out) {
    __shared__ float sz[NB*5];
    __shared__ float sA[16], sC[8], sBQ[16];
    const int tid = threadIdx.x;
    for (int i = tid; i < NB*5; i += 32) sz[i] = g_zR[i];
    if (tid < 16) sA[tid] = A_[tid];
    if (tid < 8)  sC[tid] = C_[tid];
    if (tid == 0) {
        float BQ[8];
        for (int i = 0; i < 4; ++i)
            for (int a = 0; a < 2; ++a)
                BQ[i*2+a] = B_[i*2]*Q_[a] + B_[i*2+1]*Q_[2+a];
        for (int i = 0; i < 4; ++i)
            for (int j = 0; j < 4; ++j)
                sBQ[i*4+j] = BQ[i*2]*B_[j*2] + BQ[i*2+1]*B_[j*2+1];
    }
    __syncthreads();
    if (tid >= 8) return;
    const int b = tid;
    float A[16], C[8], BQ[16];
    #pragma unroll
    for (int i = 0; i < 16; ++i) A[i] = sA[i];
    #pragma unroll
    for (int i = 0; i < 8;  ++i) C[i] = sC[i];
    #pragma unroll
    for (int i = 0; i < 16; ++i) BQ[i] = sBQ[i];

    const float* zr = sz + b*500;
    float h[4], sarr[10];
    h[0] = zr[0]; h[1] = zr[1]; h[2] = 0.f; h[3] = 0.f;
    sarr[0] = zr[2]; sarr[1] = zr[3]; sarr[2] = 0.f; sarr[3] = 0.f;
    sarr[4] = zr[4]; sarr[5] = 0.f;  sarr[6] = 0.f;
    sarr[7] = 1.f;   sarr[8] = 0.f;  sarr[9] = 1.f;

    float* ob = out + b*400;
    ob[0]=h[0]; ob[1]=h[1]; ob[2]=h[2]; ob[3]=h[3];

    for (int t = 1; t < 100; ++t) {
        const float* p = zr + t*5;
        float zt0 = p[0], zt1 = p[1], r00 = p[2], r01 = p[3], r11 = p[4];
        float hp[4];
        #pragma unroll
        for (int i = 0; i < 4; ++i)
            hp[i] = A[i*4]*h[0] + A[i*4+1]*h[1] + A[i*4+2]*h[2] + A[i*4+3]*h[3];
        float M[16];
        #pragma unroll
        for (int i = 0; i < 4; ++i)
            #pragma unroll
            for (int j = 0; j < 4; ++j)
                M[i*4+j] = A[i*4]*S_(0,j) + A[i*4+1]*S_(1,j)
                         + A[i*4+2]*S_(2,j) + A[i*4+3]*S_(3,j);
        float sp[10];
        #pragma unroll
        for (int i = 0; i < 4; ++i)
            #pragma unroll
            for (int j = 0; j < 4; ++j)
                if (j >= i)
                    sp[SIDX(i,j)] = M[i*4]*A[j*4] + M[i*4+1]*A[j*4+1]
                                  + M[i*4+2]*A[j*4+2] + M[i*4+3]*A[j*4+3] + BQ[i*4+j];
        float PT[8];
        #pragma unroll
        for (int i = 0; i < 4; ++i)
            #pragma unroll
            for (int a = 0; a < 2; ++a)
                PT[i*2+a] = SP_(i,0)*C[a*4] + SP_(i,1)*C[a*4+1]
                          + SP_(i,2)*C[a*4+2] + SP_(i,3)*C[a*4+3];
        float S00 = C[0]*PT[0]+C[1]*PT[2]+C[2]*PT[4]+C[3]*PT[6] + r00;
        float S01 = C[0]*PT[1]+C[1]*PT[3]+C[2]*PT[5]+C[3]*PT[7] + r01;
        float S10 = C[4]*PT[0]+C[5]*PT[2]+C[6]*PT[4]+C[7]*PT[6] + r01;
        float S11 = C[4]*PT[1]+C[5]*PT[3]+C[6]*PT[5]+C[7]*PT[7] + r11;
        float inv = 1.0f / (S00*S11 - S01*S10);
        float i00 =  S11*inv, i01 = -S01*inv, i10 = -S10*inv, i11 = S00*inv;
        float K[8];
        #pragma unroll
        for (int i = 0; i < 4; ++i) {
            K[i*2]   = PT[i*2]*i00 + PT[i*2+1]*i10;
            K[i*2+1] = PT[i*2]*i01 + PT[i*2+1]*i11;
        }
        float al0 = zt0 - (C[0]*hp[0]+C[1]*hp[1]+C[2]*hp[2]+C[3]*hp[3]);
        float al1 = zt1 - (C[4]*hp[0]+C[5]*hp[1]+C[6]*hp[2]+C[7]*hp[3]);
        #pragma unroll
        for (int i = 0; i < 4; ++i) h[i] = hp[i] + K[i*2]*al0 + K[i*2+1]*al1;
        float sn[10];
        #pragma unroll
        for (int i = 0; i < 4; ++i)
            #pragma unroll
            for (int j = 0; j < 4; ++j)
                if (j >= i)
                    sn[SIDX(i,j)] = SP_(i,j) - K[i*2]*PT[j*2] - K[i*2+1]*PT[j*2+1];
        #pragma unroll
        for (int i = 0; i < 10; ++i) sarr[i] = sn[i];
        float* op = ob + t*4;
        op[0]=h[0]; op[1]=h[1]; op[2]=h[2]; op[3]=h[3];
    }
}

// ---------------- launch ----------------
extern "C" void kernel_launch(void* const* d_in, const int* in_sizes, int n_in,
                              void* d_out, int out_size) {
    (void)in_sizes; (void)n_in; (void)out_size;
    const float* x    = (const float*)d_in[0];
    const float* w1   = (const float*)d_in[1];
    const float* b1   = (const float*)d_in[2];
    const float* bn1g = (const float*)d_in[3];
    const float* bn1b = (const float*)d_in[4];
    const float* w2   = (const float*)d_in[5];
    const float* b2   = (const float*)d_in[6];
    const float* bn2g = (const float*)d_in[7];
    const float* bn2b = (const float*)d_in[8];
    const float* fc1w = (const float*)d_in[9];
    const float* fc1b = (const float*)d_in[10];
    const float* fc2w = (const float*)d_in[11];
    const float* fc2b = (const float*)d_in[12];
    const float* f3zw = (const float*)d_in[13];
    const float* f3zb = (const float*)d_in[14];
    const float* f3Lw = (const float*)d_in[15];
    const float* f3Lb = (const float*)d_in[16];
    const float* Am   = (const float*)d_in[17];
    const float* Bm   = (const float*)d_in[18];
    const float* Cm   = (const float*)d_in[19];
    const float* Qm   = (const float*)d_in[20];

    (void)cudaFuncSetAttribute(k_conv1, cudaFuncAttributeMaxDynamicSharedMemorySize, SM1_BYTES);

    k_zero <<<1, 32>>>();
    k_conv1<<<NB*5, 256, SM1_BYTES>>>(x, w1, b1);
    k_conv2<<<NB, 128>>>(w2, b2, bn1g, bn1b);
    k_fc   <<<13, 64>>>(fc1w, fc1b, fc2w, fc2b, f3zw, f3zb, f3Lw, f3Lb, bn2g, bn2b);
    k_kf   <<<1, 32>>>(Am, Bm, Cm, Qm, (float*)d_out);
}